// round 11
// baseline (speedup 1.0000x reference)
// R11: kernelM eliminated — kernelA does X@Wc -> T (smem), T@Wv -> xv, X@Ws -> skip,
//      all on tensor cores (tf32 3-term split). kernelA is now the FIRST launch so
//      the positional ncu capture finally profiles it. kernelB = R5 known-good.
#include <cuda_runtime.h>
#include <cuda_fp16.h>
#include <cstdint>

#define BN_TOTAL 16384      // B*N = 4*4096
#define OUT1_OFF 1048576    // B*N*1*64
#define OUT2_OFF 4194304    // OUT1_OFF + B*N*3*64

__device__ __align__(16) __half g_xvh[BN_TOTAL * 9 * 64];   // fp16 gathered tensor
__device__ __align__(16) float  g_skip[BN_TOTAL * 9 * 64];  // fp32 skip path

__device__ __forceinline__ uint32_t f2tf(float x) {
    uint32_t r;
    asm("cvt.rna.tf32.f32 %0, %1;" : "=r"(r) : "f"(x));
    return r;
}
__device__ __forceinline__ float tf2f(uint32_t u) { return __uint_as_float(u); }

#define MMA_TF32(acc, a0, a1, a2, a3, b0, b1)                                   \
    asm volatile(                                                               \
        "mma.sync.aligned.m16n8k8.row.col.f32.tf32.tf32.f32 "                   \
        "{%0,%1,%2,%3}, {%4,%5,%6,%7}, {%8,%9}, {%0,%1,%2,%3};"                 \
        : "+f"((acc)[0]), "+f"((acc)[1]), "+f"((acc)[2]), "+f"((acc)[3])        \
        : "r"(a0), "r"(a1), "r"(a2), "r"(a3), "r"(b0), "r"(b1))

// Convert a float pair to tf32 hi/lo splits
#define TFSPLIT(hi, lo, f) do { hi = f2tf(f); lo = f2tf((f) - tf2f(hi)); } while (0)

// ---------------------------------------------------------------------------
// Kernel A: per-64-row-tile, all-tensor-core, M-free.
//   stage1 (dual): T = X@Wc, S = X@Ws      (shared A-fragments)
//   T -> smem (overwrites Wc tile)
//   stage2:        xv = T@Wv
// Warp w: m-tile = (w&3)*16 rows, n-half = (w>>2)*32 cols.
// smem: sX, sWcT(->T), sWvT, sWsT, each [64][ASTR] fp32 = 69632 B dynamic.
// ---------------------------------------------------------------------------
#define ASTR 68
__global__ __launch_bounds__(256) void kernelA(
    const float* __restrict__ x0, const float* __restrict__ x1, const float* __restrict__ x2,
    const float* __restrict__ mask,
    const float* __restrict__ Wc0, const float* __restrict__ Wc1, const float* __restrict__ Wc2,
    const float* __restrict__ Wv0, const float* __restrict__ Wv1, const float* __restrict__ Wv2,
    const float* __restrict__ Ws0, const float* __restrict__ Ws1, const float* __restrict__ Ws2)
{
    extern __shared__ __align__(16) float smem[];
    float* sX   = smem;                 // [64][ASTR] X row r, col k
    float* sT   = smem + 64 * ASTR;     // Wc transposed, then T [row][c1]
    float* sWvT = smem + 2 * 64 * ASTR; // [c2][c1]
    float* sWsT = smem + 3 * 64 * ASTR; // [c2][k]

    int bx = blockIdx.x, tid = threadIdx.x;
    int tile, md, moff;
    const float *x, *Wc, *Wv, *Ws;
    if (bx < 256)       { tile = bx;        x = x0; Wc = Wc0; Wv = Wv0; Ws = Ws0; md = 1; moff = 0; }
    else if (bx < 1024) { tile = bx - 256;  x = x1; Wc = Wc1; Wv = Wv1; Ws = Ws1; md = 3; moff = 1; }
    else                { tile = bx - 1024; x = x2; Wc = Wc2; Wv = Wv2; Ws = Ws2; md = 5; moff = 4; }
    int row0 = tile * 64;

    // x tile with mask applied
    const float* xb = x + (size_t)row0 * 64;
    #pragma unroll
    for (int it = 0; it < 4; ++it) {
        int i = tid * 4 + it * 1024;
        int r = i >> 6, c = i & 63;
        float4 v = *(const float4*)(xb + i);
        float mk = mask[(row0 + r) / md];
        float* dst = sX + r * ASTR + c;
        dst[0] = v.x * mk; dst[1] = v.y * mk; dst[2] = v.z * mk; dst[3] = v.w * mk;
    }
    // Transposed weight tiles: sW?T[c * ASTR + k] = W[k*64 + c]
    #pragma unroll
    for (int it = 0; it < 16; ++it) {
        int i = tid + it * 256;
        int k = i >> 6, c = i & 63;
        sT[c * ASTR + k]   = Wc[i];
        sWvT[c * ASTR + k] = Wv[i];
        sWsT[c * ASTR + k] = Ws[i];
    }
    __syncthreads();

    int wp = tid >> 5, lane = tid & 31;
    int gid = lane >> 2, tig = lane & 3;
    int m0 = (wp & 3) * 16;         // 16-row m-tile
    int cq = (wp >> 2) * 32;        // 32-col n-half (4 n-tiles of 8)

    // ---------------- stage 1: T = X@Wc (dual with S = X@Ws) ----------------
    float accT[4][4], accS[4][4];
    #pragma unroll
    for (int nt = 0; nt < 4; ++nt)
        #pragma unroll
        for (int q = 0; q < 4; ++q) { accT[nt][q] = 0.f; accS[nt][q] = 0.f; }

    #pragma unroll
    for (int k0 = 0; k0 < 64; k0 += 8) {
        const float* xr0 = sX + (m0 + gid) * ASTR + k0;
        const float* xr1 = xr0 + 8 * ASTR;
        float f0 = xr0[tig], f1 = xr1[tig], f2 = xr0[tig + 4], f3 = xr1[tig + 4];
        uint32_t ah0, al0, ah1, al1, ah2, al2, ah3, al3;
        TFSPLIT(ah0, al0, f0); TFSPLIT(ah1, al1, f1);
        TFSPLIT(ah2, al2, f2); TFSPLIT(ah3, al3, f3);

        #pragma unroll
        for (int nt = 0; nt < 4; ++nt) {
            int c0 = cq + nt * 8;
            const float* wcp = sT + (c0 + gid) * ASTR + k0;      // still Wc here
            float bc0 = wcp[tig], bc1 = wcp[tig + 4];
            uint32_t bch0, bcl0, bch1, bcl1;
            TFSPLIT(bch0, bcl0, bc0); TFSPLIT(bch1, bcl1, bc1);
            MMA_TF32(accT[nt], ah0, ah1, ah2, ah3, bch0, bch1);
            MMA_TF32(accT[nt], ah0, ah1, ah2, ah3, bcl0, bcl1);
            MMA_TF32(accT[nt], al0, al1, al2, al3, bch0, bch1);

            const float* wsp = sWsT + (c0 + gid) * ASTR + k0;
            float bs0 = wsp[tig], bs1 = wsp[tig + 4];
            uint32_t bsh0, bsl0, bsh1, bsl1;
            TFSPLIT(bsh0, bsl0, bs0); TFSPLIT(bsh1, bsl1, bs1);
            MMA_TF32(accS[nt], ah0, ah1, ah2, ah3, bsh0, bsh1);
            MMA_TF32(accS[nt], ah0, ah1, ah2, ah3, bsl0, bsl1);
            MMA_TF32(accS[nt], al0, al1, al2, al3, bsh0, bsh1);
        }
    }

    __syncthreads();   // all reads of Wc done; safe to overwrite with T

    // Store T (fragment rows m0+gid, m0+gid+8; cols cq+nt*8+2tig..+1)
    #pragma unroll
    for (int nt = 0; nt < 4; ++nt) {
        int c = cq + nt * 8 + 2 * tig;
        *(float2*)(sT + (m0 + gid) * ASTR + c)     = make_float2(accT[nt][0], accT[nt][1]);
        *(float2*)(sT + (m0 + gid + 8) * ASTR + c) = make_float2(accT[nt][2], accT[nt][3]);
    }
    __syncthreads();

    // ---------------- stage 2: xv = T@Wv ----------------
    float accM[4][4];
    #pragma unroll
    for (int nt = 0; nt < 4; ++nt)
        #pragma unroll
        for (int q = 0; q < 4; ++q) accM[nt][q] = 0.f;

    #pragma unroll
    for (int k0 = 0; k0 < 64; k0 += 8) {
        const float* tr0 = sT + (m0 + gid) * ASTR + k0;
        const float* tr1 = tr0 + 8 * ASTR;
        float f0 = tr0[tig], f1 = tr1[tig], f2 = tr0[tig + 4], f3 = tr1[tig + 4];
        uint32_t ah0, al0, ah1, al1, ah2, al2, ah3, al3;
        TFSPLIT(ah0, al0, f0); TFSPLIT(ah1, al1, f1);
        TFSPLIT(ah2, al2, f2); TFSPLIT(ah3, al3, f3);

        #pragma unroll
        for (int nt = 0; nt < 4; ++nt) {
            int c0 = cq + nt * 8;
            const float* wvp = sWvT + (c0 + gid) * ASTR + k0;
            float bv0 = wvp[tig], bv1 = wvp[tig + 4];
            uint32_t bvh0, bvl0, bvh1, bvl1;
            TFSPLIT(bvh0, bvl0, bv0); TFSPLIT(bvh1, bvl1, bv1);
            MMA_TF32(accM[nt], ah0, ah1, ah2, ah3, bvh0, bvh1);
            MMA_TF32(accM[nt], ah0, ah1, ah2, ah3, bvl0, bvl1);
            MMA_TF32(accM[nt], al0, al1, al2, al3, bvh0, bvh1);
        }
    }

    // Epilogue: store fp16 xv + fp32 skip
    int r0g = row0 + m0 + gid;
    int r1g = r0g + 8;
    int bn0 = r0g / md, bn1 = r1g / md;
    int base0 = (bn0 * 9 + moff + (r0g - bn0 * md)) * 64;
    int base1 = (bn1 * 9 + moff + (r1g - bn1 * md)) * 64;
    #pragma unroll
    for (int nt = 0; nt < 4; ++nt) {
        int col = cq + nt * 8 + 2 * tig;
        *(__half2*)(g_xvh + base0 + col) = __floats2half2_rn(accM[nt][0], accM[nt][1]);
        *(__half2*)(g_xvh + base1 + col) = __floats2half2_rn(accM[nt][2], accM[nt][3]);
        *(float2*)(g_skip + base0 + col) = make_float2(accS[nt][0], accS[nt][1]);
        *(float2*)(g_skip + base1 + col) = make_float2(accS[nt][2], accS[nt][3]);
    }
}

// ---------------------------------------------------------------------------
// Kernel B (R5 known-good): one block per point, 288 threads.
// ---------------------------------------------------------------------------
__global__ __launch_bounds__(288) void kernelB(
    const float* __restrict__ points, const int* __restrict__ pidx,
    const float* __restrict__ mask, float* __restrict__ out)
{
    __shared__ float sw[32];
    __shared__ int   srow[32];
    __shared__ int   snnz;
    __shared__ __align__(8) float vbuf[576];
    __shared__ __align__(8) float fbuf[192];

    int bn = blockIdx.x;
    int tid = threadIdx.x;

    if (tid < 32) {
        int idx  = pidx[bn * 32 + tid];
        int b    = bn >> 12;                 // N = 4096
        int prow = (b << 12) + idx;
        float cx = points[bn * 3 + 0], cy = points[bn * 3 + 1], cz = points[bn * 3 + 2];
        float dx = points[prow * 3 + 0] - cx;
        float dy = points[prow * 3 + 1] - cy;
        float dz = points[prow * 3 + 2] - cz;
        float r  = sqrtf(fmaf(dx, dx, fmaf(dy, dy, fmaf(dz, dz, 1e-12f))));
        float w  = 1.0f - r / 0.4f;
        bool act = w > 0.0f;
        unsigned bal = __ballot_sync(0xffffffffu, act);
        int pos = __popc(bal & ((1u << tid) - 1u));
        if (act) { sw[pos] = w; srow[pos] = prow * 576; }
        if (tid == 0) snnz = __popc(bal);
    }
    __syncthreads();

    int m = tid >> 5, j = tid & 31;
    int off = m * 64 + j * 2;
    int nnz = snnz;

    float ax = 0.f, ay = 0.f;
    int i = 0;
    for (; i + 4 <= nnz; i += 4) {
        float w0 = sw[i + 0], w1 = sw[i + 1], w2 = sw[i + 2], w3 = sw[i + 3];
        float2 p0 = __half22float2(*(const __half2*)(g_xvh + srow[i + 0] + off));
        float2 p1 = __half22float2(*(const __half2*)(g_xvh + srow[i + 1] + off));
        float2 p2 = __half22float2(*(const __half2*)(g_xvh + srow[i + 2] + off));
        float2 p3 = __half22float2(*(const __half2*)(g_xvh + srow[i + 3] + off));
        ax = fmaf(w0, p0.x, ax); ay = fmaf(w0, p0.y, ay);
        ax = fmaf(w1, p1.x, ax); ay = fmaf(w1, p1.y, ay);
        ax = fmaf(w2, p2.x, ax); ay = fmaf(w2, p2.y, ay);
        ax = fmaf(w3, p3.x, ax); ay = fmaf(w3, p3.y, ay);
    }
    for (; i < nnz; ++i) {
        float w0 = sw[i];
        float2 p0 = __half22float2(*(const __half2*)(g_xvh + srow[i] + off));
        ax = fmaf(w0, p0.x, ax); ay = fmaf(w0, p0.y, ay);
    }
    vbuf[off] = ax; vbuf[off + 1] = ay;
    __syncthreads();

    if (tid < 192) {
        int d  = tid >> 6, co = tid & 63;
        int m0 = (d == 0) ? 0 : (d == 1 ? 1 : 4);
        int mc = (d == 0) ? 1 : (d == 1 ? 3 : 5);
        float S = 0.f;
        for (int mm = 0; mm < mc; ++mm) {
            float v = vbuf[(m0 + mm) * 64 + co];
            S = fmaf(v, v, S);
        }
        float scale = rsqrtf(S + 0.01f);
        float f = scale;
        if (d > 0) {
            float S2 = S * scale * scale;             // = sum of normalized v^2
            float nn = sqrtf(S2 + 0.01f);
            f = scale * (1.0f / (1.0f + __expf(-nn)));
        }
        fbuf[tid] = f;
    }
    __syncthreads();

    float mk = mask[bn];
    int d = (m == 0) ? 0 : (m < 4 ? 1 : 2);
    float2 f2 = *(const float2*)&fbuf[d * 64 + 2 * j];
    float a0 = ax * f2.x, a1 = ay * f2.y;
    if (m == 0) { a0 = fmaxf(a0, 0.f); a1 = fmaxf(a1, 0.f); }

    float2 sk = *(const float2*)(g_skip + bn * 576 + off);
    float o0 = (a0 + sk.x) * mk;
    float o1 = (a1 + sk.y) * mk;

    float* op;
    if (m == 0)      op = out + bn * 64 + 2 * j;
    else if (m < 4)  op = out + OUT1_OFF + (bn * 3 + (m - 1)) * 64 + 2 * j;
    else             op = out + OUT2_OFF + (bn * 5 + (m - 4)) * 64 + 2 * j;
    *(float2*)op = make_float2(o0, o1);
}

// ---------------------------------------------------------------------------
extern "C" void kernel_launch(void* const* d_in, const int* in_sizes, int n_in,
                              void* d_out, int out_size) {
    const float* x0     = (const float*)d_in[0];
    const float* x1     = (const float*)d_in[1];
    const float* x2     = (const float*)d_in[2];
    const float* points = (const float*)d_in[3];
    const int*   pidx   = (const int*)  d_in[4];
    const float* mask   = (const float*)d_in[5];
    const float* Wc0    = (const float*)d_in[6];
    const float* Wc1    = (const float*)d_in[7];
    const float* Wc2    = (const float*)d_in[8];
    const float* Wv0    = (const float*)d_in[9];
    const float* Wv1    = (const float*)d_in[10];
    const float* Wv2    = (const float*)d_in[11];
    const float* Ws0    = (const float*)d_in[12];
    const float* Ws1    = (const float*)d_in[13];
    const float* Ws2    = (const float*)d_in[14];
    float* out = (float*)d_out;

    const int smemA = 4 * 64 * ASTR * sizeof(float);   // 69632 B
    cudaFuncSetAttribute(kernelA, cudaFuncAttributeMaxDynamicSharedMemorySize, smemA);

    kernelA<<<2304, 256, smemA>>>(x0, x1, x2, mask,
                                  Wc0, Wc1, Wc2, Wv0, Wv1, Wv2, Ws0, Ws1, Ws2);
    kernelB<<<16384, 288>>>(points, pidx, mask, out);
}

// round 12
// speedup vs baseline: 1.2525x; 1.2525x over previous
// R12: R10 structure restored (M + tensor-core A + R5 B).
//      Single change vs R10: kernelA weights in natural [k][c] layout ->
//      float4 conflict-free prologue, conflict-free B-fragment LDS.
#include <cuda_runtime.h>
#include <cuda_fp16.h>
#include <cstdint>

#define BN_TOTAL 16384      // B*N = 4*4096
#define OUT1_OFF 1048576    // B*N*1*64
#define OUT2_OFF 4194304    // OUT1_OFF + B*N*3*64

__device__ __align__(16) float  g_Mv[3 * 64 * 64];          // Mv = Wc@Wv, [c][co] natural
__device__ __align__(16) __half g_xvh[BN_TOTAL * 9 * 64];   // fp16 gathered tensor
__device__ __align__(16) float  g_skip[BN_TOTAL * 9 * 64];  // fp32 skip path

__device__ __forceinline__ uint32_t f2tf(float x) {
    uint32_t r;
    asm("cvt.rna.tf32.f32 %0, %1;" : "=r"(r) : "f"(x));
    return r;
}
__device__ __forceinline__ float tf2f(uint32_t u) { return __uint_as_float(u); }

#define MMA_TF32(acc, a0, a1, a2, a3, b0, b1)                                   \
    asm volatile(                                                               \
        "mma.sync.aligned.m16n8k8.row.col.f32.tf32.tf32.f32 "                   \
        "{%0,%1,%2,%3}, {%4,%5,%6,%7}, {%8,%9}, {%0,%1,%2,%3};"                 \
        : "+f"((acc)[0]), "+f"((acc)[1]), "+f"((acc)[2]), "+f"((acc)[3])        \
        : "r"(a0), "r"(a1), "r"(a2), "r"(a3), "r"(b0), "r"(b1))

#define TFSPLIT(hi, lo, f) do { hi = f2tf(f); lo = f2tf((f) - tf2f(hi)); } while (0)

// ---------------------------------------------------------------------------
// Kernel M: Mv_d = Wconv_d @ Wv_d.  12 blocks = 3 degrees x 4 col-slices(16).
// ---------------------------------------------------------------------------
__global__ __launch_bounds__(256) void kernelM(
    const float* __restrict__ Wc0, const float* __restrict__ Wc1,
    const float* __restrict__ Wc2, const float* __restrict__ Wv0,
    const float* __restrict__ Wv1, const float* __restrict__ Wv2)
{
    __shared__ float sWc[64 * 65];
    __shared__ __align__(16) float sWvS[64 * 16];
    int d = blockIdx.x >> 2, sl = blockIdx.x & 3;
    int g0 = sl * 16;
    const float* Wc = (d == 0) ? Wc0 : (d == 1 ? Wc1 : Wc2);
    const float* Wv = (d == 0) ? Wv0 : (d == 1 ? Wv1 : Wv2);
    int tid = threadIdx.x;

    #pragma unroll
    for (int it = 0; it < 16; ++it) {
        int i = tid + it * 256;
        int k = i & 63, c = i >> 6;
        sWc[c * 65 + k] = Wc[i];
    }
    {
        int i = tid * 4;
        int k = i >> 4, cc = i & 15;
        *(float4*)(sWvS + k * 16 + cc) = *(const float4*)(Wv + k * 64 + g0 + cc);
    }
    __syncthreads();

    int c = tid & 63, cg = (tid >> 6) * 4;
    float4 acc = make_float4(0.f, 0.f, 0.f, 0.f);
    #pragma unroll 8
    for (int k = 0; k < 64; ++k) {
        float a = sWc[c * 65 + k];
        float4 b = *(const float4*)(sWvS + k * 16 + cg);
        acc.x = fmaf(a, b.x, acc.x);
        acc.y = fmaf(a, b.y, acc.y);
        acc.z = fmaf(a, b.z, acc.z);
        acc.w = fmaf(a, b.w, acc.w);
    }
    *(float4*)(g_Mv + d * 4096 + c * 64 + g0 + cg) = acc;
}

// ---------------------------------------------------------------------------
// Kernel A: fused dual GEMM per 64-row tile on tensor cores.
//   xv = (x*mask)@Mv -> g_xvh (fp16);  skip = (x*mask)@Ws -> g_skip (fp32)
// tf32 3-term split (Xhi*Whi + Xhi*Wlo + Xlo*Whi), fp32-like accuracy.
// Weights staged in NATURAL [k][c] layout, pad ASTR=68:
//   - prologue: float4 LDG -> float4 STS, conflict-free (banks 4k+c)
//   - B frags:  sW[(k0+tig)*68 + c0+gid], banks 4*tig+gid -> conflict-free
// smem: sX + sWm + sWs = 3 * 64*68*4 = 52224 B -> 4 blocks/SM.
// ---------------------------------------------------------------------------
#define ASTR 68
__global__ __launch_bounds__(256) void kernelA(
    const float* __restrict__ x0, const float* __restrict__ x1, const float* __restrict__ x2,
    const float* __restrict__ mask,
    const float* __restrict__ Ws0, const float* __restrict__ Ws1, const float* __restrict__ Ws2)
{
    extern __shared__ __align__(16) float smem[];
    float* sX  = smem;                 // [64][ASTR] X row r, col k
    float* sWm = smem + 64 * ASTR;     // [64][ASTR] Mv natural [k][c]
    float* sWs = smem + 2 * 64 * ASTR; // [64][ASTR] Ws natural [k][c]

    int bx = blockIdx.x, tid = threadIdx.x;
    int tile, md, moff;
    const float *x, *Ws, *Wm;
    if (bx < 256)       { tile = bx;        x = x0; Ws = Ws0; Wm = g_Mv;        md = 1; moff = 0; }
    else if (bx < 1024) { tile = bx - 256;  x = x1; Ws = Ws1; Wm = g_Mv + 4096; md = 3; moff = 1; }
    else                { tile = bx - 1024; x = x2; Ws = Ws2; Wm = g_Mv + 8192; md = 5; moff = 4; }
    int row0 = tile * 64;

    // x tile with mask applied
    const float* xb = x + (size_t)row0 * 64;
    #pragma unroll
    for (int it = 0; it < 4; ++it) {
        int i = tid * 4 + it * 1024;
        int r = i >> 6, c = i & 63;
        float4 v = *(const float4*)(xb + i);
        float mk = mask[(row0 + r) / md];
        float* dst = sX + r * ASTR + c;
        dst[0] = v.x * mk; dst[1] = v.y * mk; dst[2] = v.z * mk; dst[3] = v.w * mk;
    }
    // Weights: natural layout, vectorized, conflict-free
    #pragma unroll
    for (int it = 0; it < 4; ++it) {
        int i = tid * 4 + it * 1024;
        int k = i >> 6, c = i & 63;
        *(float4*)(sWm + k * ASTR + c) = *(const float4*)(Wm + i);
        *(float4*)(sWs + k * ASTR + c) = *(const float4*)(Ws + i);
    }
    __syncthreads();

    int wp = tid >> 5, lane = tid & 31;
    int gid = lane >> 2, tig = lane & 3;
    int m0 = (wp & 3) * 16;         // 16-row m-tile
    int cq = (wp >> 2) * 32;        // 32-col n-half (4 n-tiles of 8)

    float accM[4][4], accS[4][4];
    #pragma unroll
    for (int nt = 0; nt < 4; ++nt)
        #pragma unroll
        for (int q = 0; q < 4; ++q) { accM[nt][q] = 0.f; accS[nt][q] = 0.f; }

    #pragma unroll
    for (int k0 = 0; k0 < 64; k0 += 8) {
        // A fragments (m16k8 tf32), hi/lo split
        const float* xr0 = sX + (m0 + gid) * ASTR + k0;
        const float* xr1 = xr0 + 8 * ASTR;
        float f0 = xr0[tig], f1 = xr1[tig], f2 = xr0[tig + 4], f3 = xr1[tig + 4];
        uint32_t ah0, al0, ah1, al1, ah2, al2, ah3, al3;
        TFSPLIT(ah0, al0, f0); TFSPLIT(ah1, al1, f1);
        TFSPLIT(ah2, al2, f2); TFSPLIT(ah3, al3, f3);

        #pragma unroll
        for (int nt = 0; nt < 4; ++nt) {
            int c0 = cq + nt * 8;
            // B fragment: B[k][n] natural; need B[k0+tig][c0+gid], B[k0+tig+4][c0+gid]
            const float* wmp = sWm + (k0 + tig) * ASTR + c0 + gid;
            float bm0 = wmp[0], bm1 = wmp[4 * ASTR];
            uint32_t bmh0, bml0, bmh1, bml1;
            TFSPLIT(bmh0, bml0, bm0); TFSPLIT(bmh1, bml1, bm1);
            MMA_TF32(accM[nt], ah0, ah1, ah2, ah3, bmh0, bmh1);
            MMA_TF32(accM[nt], ah0, ah1, ah2, ah3, bml0, bml1);
            MMA_TF32(accM[nt], al0, al1, al2, al3, bmh0, bmh1);

            const float* wsp = sWs + (k0 + tig) * ASTR + c0 + gid;
            float bs0 = wsp[0], bs1 = wsp[4 * ASTR];
            uint32_t bsh0, bsl0, bsh1, bsl1;
            TFSPLIT(bsh0, bsl0, bs0); TFSPLIT(bsh1, bsl1, bs1);
            MMA_TF32(accS[nt], ah0, ah1, ah2, ah3, bsh0, bsh1);
            MMA_TF32(accS[nt], ah0, ah1, ah2, ah3, bsl0, bsl1);
            MMA_TF32(accS[nt], al0, al1, al2, al3, bsh0, bsh1);
        }
    }

    // Epilogue: D frag rows (m0+gid), (m0+gid+8); cols cq+nt*8+2tig, +1
    int r0g = row0 + m0 + gid;
    int r1g = r0g + 8;
    int bn0 = r0g / md, bn1 = r1g / md;
    int base0 = (bn0 * 9 + moff + (r0g - bn0 * md)) * 64;
    int base1 = (bn1 * 9 + moff + (r1g - bn1 * md)) * 64;
    #pragma unroll
    for (int nt = 0; nt < 4; ++nt) {
        int col = cq + nt * 8 + 2 * tig;
        *(__half2*)(g_xvh + base0 + col) = __floats2half2_rn(accM[nt][0], accM[nt][1]);
        *(__half2*)(g_xvh + base1 + col) = __floats2half2_rn(accM[nt][2], accM[nt][3]);
        *(float2*)(g_skip + base0 + col) = make_float2(accS[nt][0], accS[nt][1]);
        *(float2*)(g_skip + base1 + col) = make_float2(accS[nt][2], accS[nt][3]);
    }
}

// ---------------------------------------------------------------------------
// Kernel B (R5 known-good, measured 57.4us): one block per point, 288 threads.
// ---------------------------------------------------------------------------
__global__ __launch_bounds__(288) void kernelB(
    const float* __restrict__ points, const int* __restrict__ pidx,
    const float* __restrict__ mask, float* __restrict__ out)
{
    __shared__ float sw[32];
    __shared__ int   srow[32];
    __shared__ int   snnz;
    __shared__ __align__(8) float vbuf[576];
    __shared__ __align__(8) float fbuf[192];

    int bn = blockIdx.x;
    int tid = threadIdx.x;

    if (tid < 32) {
        int idx  = pidx[bn * 32 + tid];
        int b    = bn >> 12;                 // N = 4096
        int prow = (b << 12) + idx;
        float cx = points[bn * 3 + 0], cy = points[bn * 3 + 1], cz = points[bn * 3 + 2];
        float dx = points[prow * 3 + 0] - cx;
        float dy = points[prow * 3 + 1] - cy;
        float dz = points[prow * 3 + 2] - cz;
        float r  = sqrtf(fmaf(dx, dx, fmaf(dy, dy, fmaf(dz, dz, 1e-12f))));
        float w  = 1.0f - r / 0.4f;
        bool act = w > 0.0f;
        unsigned bal = __ballot_sync(0xffffffffu, act);
        int pos = __popc(bal & ((1u << tid) - 1u));
        if (act) { sw[pos] = w; srow[pos] = prow * 576; }
        if (tid == 0) snnz = __popc(bal);
    }
    __syncthreads();

    int m = tid >> 5, j = tid & 31;
    int off = m * 64 + j * 2;
    int nnz = snnz;

    float ax = 0.f, ay = 0.f;
    int i = 0;
    for (; i + 4 <= nnz; i += 4) {
        float w0 = sw[i + 0], w1 = sw[i + 1], w2 = sw[i + 2], w3 = sw[i + 3];
        float2 p0 = __half22float2(*(const __half2*)(g_xvh + srow[i + 0] + off));
        float2 p1 = __half22float2(*(const __half2*)(g_xvh + srow[i + 1] + off));
        float2 p2 = __half22float2(*(const __half2*)(g_xvh + srow[i + 2] + off));
        float2 p3 = __half22float2(*(const __half2*)(g_xvh + srow[i + 3] + off));
        ax = fmaf(w0, p0.x, ax); ay = fmaf(w0, p0.y, ay);
        ax = fmaf(w1, p1.x, ax); ay = fmaf(w1, p1.y, ay);
        ax = fmaf(w2, p2.x, ax); ay = fmaf(w2, p2.y, ay);
        ax = fmaf(w3, p3.x, ax); ay = fmaf(w3, p3.y, ay);
    }
    for (; i < nnz; ++i) {
        float w0 = sw[i];
        float2 p0 = __half22float2(*(const __half2*)(g_xvh + srow[i] + off));
        ax = fmaf(w0, p0.x, ax); ay = fmaf(w0, p0.y, ay);
    }
    vbuf[off] = ax; vbuf[off + 1] = ay;
    __syncthreads();

    if (tid < 192) {
        int d  = tid >> 6, co = tid & 63;
        int m0 = (d == 0) ? 0 : (d == 1 ? 1 : 4);
        int mc = (d == 0) ? 1 : (d == 1 ? 3 : 5);
        float S = 0.f;
        for (int mm = 0; mm < mc; ++mm) {
            float v = vbuf[(m0 + mm) * 64 + co];
            S = fmaf(v, v, S);
        }
        float scale = rsqrtf(S + 0.01f);
        float f = scale;
        if (d > 0) {
            float S2 = S * scale * scale;             // = sum of normalized v^2
            float nn = sqrtf(S2 + 0.01f);
            f = scale * (1.0f / (1.0f + __expf(-nn)));
        }
        fbuf[tid] = f;
    }
    __syncthreads();

    float mk = mask[bn];
    int d = (m == 0) ? 0 : (m < 4 ? 1 : 2);
    float2 f2 = *(const float2*)&fbuf[d * 64 + 2 * j];
    float a0 = ax * f2.x, a1 = ay * f2.y;
    if (m == 0) { a0 = fmaxf(a0, 0.f); a1 = fmaxf(a1, 0.f); }

    float2 sk = *(const float2*)(g_skip + bn * 576 + off);
    float o0 = (a0 + sk.x) * mk;
    float o1 = (a1 + sk.y) * mk;

    float* op;
    if (m == 0)      op = out + bn * 64 + 2 * j;
    else if (m < 4)  op = out + OUT1_OFF + (bn * 3 + (m - 1)) * 64 + 2 * j;
    else             op = out + OUT2_OFF + (bn * 5 + (m - 4)) * 64 + 2 * j;
    *(float2*)op = make_float2(o0, o1);
}

// ---------------------------------------------------------------------------
extern "C" void kernel_launch(void* const* d_in, const int* in_sizes, int n_in,
                              void* d_out, int out_size) {
    const float* x0     = (const float*)d_in[0];
    const float* x1     = (const float*)d_in[1];
    const float* x2     = (const float*)d_in[2];
    const float* points = (const float*)d_in[3];
    const int*   pidx   = (const int*)  d_in[4];
    const float* mask   = (const float*)d_in[5];
    const float* Wc0    = (const float*)d_in[6];
    const float* Wc1    = (const float*)d_in[7];
    const float* Wc2    = (const float*)d_in[8];
    const float* Wv0    = (const float*)d_in[9];
    const float* Wv1    = (const float*)d_in[10];
    const float* Wv2    = (const float*)d_in[11];
    const float* Ws0    = (const float*)d_in[12];
    const float* Ws1    = (const float*)d_in[13];
    const float* Ws2    = (const float*)d_in[14];
    float* out = (float*)d_out;

    const int smemA = 3 * 64 * ASTR * sizeof(float);   // 52224 B
    cudaFuncSetAttribute(kernelA, cudaFuncAttributeMaxDynamicSharedMemorySize, smemA);

    kernelM<<<12, 256>>>(Wc0, Wc1, Wc2, Wv0, Wv1, Wv2);
    kernelA<<<2304, 256, smemA>>>(x0, x1, x2, mask, Ws0, Ws1, Ws2);
    kernelB<<<16384, 288>>>(points, pidx, mask, out);
}

// round 13
// speedup vs baseline: 1.6929x; 1.3517x over previous
// R13: kernelA on fp16 m16n8k16 single-term MMA (weights pre-packed half2 by kernelM).
//      kernelB = R5 known-good (57.4us measured). Error budget: fp16 inputs add
//      ~1.2e-4 (same order as existing fp16 xv storage); inputs are seed-fixed.
#include <cuda_runtime.h>
#include <cuda_fp16.h>
#include <cstdint>

#define BN_TOTAL 16384      // B*N = 4*4096
#define OUT1_OFF 1048576    // B*N*1*64
#define OUT2_OFF 4194304    // OUT1_OFF + B*N*3*64

// Packed half2 weights: [deg][k2=32][c=64], element = half2(W[2k2][c], W[2k2+1][c])
__device__ __align__(16) uint32_t g_Mvh[3 * 2048];
__device__ __align__(16) uint32_t g_Wsh[3 * 2048];
__device__ __align__(16) __half  g_xvh[BN_TOTAL * 9 * 64];   // fp16 gathered tensor
__device__ __align__(16) float   g_skip[BN_TOTAL * 9 * 64];  // fp32 skip path

__device__ __forceinline__ uint32_t h2u(__half2 h) { return *(uint32_t*)&h; }

#define MMA_F16(acc, a0, a1, a2, a3, b0, b1)                                    \
    asm volatile(                                                               \
        "mma.sync.aligned.m16n8k16.row.col.f32.f16.f16.f32 "                    \
        "{%0,%1,%2,%3}, {%4,%5,%6,%7}, {%8,%9}, {%0,%1,%2,%3};"                 \
        : "+f"((acc)[0]), "+f"((acc)[1]), "+f"((acc)[2]), "+f"((acc)[3])        \
        : "r"(a0), "r"(a1), "r"(a2), "r"(a3), "r"(b0), "r"(b1))

// ---------------------------------------------------------------------------
// Kernel M: Mv_d = Wconv_d @ Wv_d, then emit k-pair-packed half2 Mv and Ws.
// 12 blocks = 3 degrees x 4 col-slices(16).
// ---------------------------------------------------------------------------
__global__ __launch_bounds__(256) void kernelM(
    const float* __restrict__ Wc0, const float* __restrict__ Wc1,
    const float* __restrict__ Wc2, const float* __restrict__ Wv0,
    const float* __restrict__ Wv1, const float* __restrict__ Wv2,
    const float* __restrict__ Ws0, const float* __restrict__ Ws1,
    const float* __restrict__ Ws2)
{
    __shared__ float sWc[64 * 65];
    __shared__ __align__(16) float sWvS[64 * 16];
    __shared__ __align__(16) float sOut[64 * 16];
    int d = blockIdx.x >> 2, sl = blockIdx.x & 3;
    int g0 = sl * 16;
    const float* Wc = (d == 0) ? Wc0 : (d == 1 ? Wc1 : Wc2);
    const float* Wv = (d == 0) ? Wv0 : (d == 1 ? Wv1 : Wv2);
    const float* Ws = (d == 0) ? Ws0 : (d == 1 ? Ws1 : Ws2);
    int tid = threadIdx.x;

    #pragma unroll
    for (int it = 0; it < 16; ++it) {
        int i = tid + it * 256;
        int k = i & 63, c = i >> 6;
        sWc[c * 65 + k] = Wc[i];
    }
    {
        int i = tid * 4;
        int k = i >> 4, cc = i & 15;
        *(float4*)(sWvS + k * 16 + cc) = *(const float4*)(Wv + k * 64 + g0 + cc);
    }
    // Ws packing (independent of smem): 512 half2 per block slice
    #pragma unroll
    for (int j = 0; j < 2; ++j) {
        int idx = tid + j * 256;
        int k2 = idx >> 4, cc = idx & 15;
        float lo = Ws[(2 * k2) * 64 + g0 + cc];
        float hi = Ws[(2 * k2 + 1) * 64 + g0 + cc];
        g_Wsh[d * 2048 + k2 * 64 + g0 + cc] = h2u(__floats2half2_rn(lo, hi));
    }
    __syncthreads();

    int c = tid & 63, cg = (tid >> 6) * 4;
    float4 acc = make_float4(0.f, 0.f, 0.f, 0.f);
    #pragma unroll 8
    for (int k = 0; k < 64; ++k) {
        float a = sWc[c * 65 + k];
        float4 b = *(const float4*)(sWvS + k * 16 + cg);
        acc.x = fmaf(a, b.x, acc.x);
        acc.y = fmaf(a, b.y, acc.y);
        acc.z = fmaf(a, b.z, acc.z);
        acc.w = fmaf(a, b.w, acc.w);
    }
    *(float4*)(sOut + c * 16 + cg) = acc;
    __syncthreads();

    // Mv packing from sOut
    #pragma unroll
    for (int j = 0; j < 2; ++j) {
        int idx = tid + j * 256;
        int k2 = idx >> 4, cc = idx & 15;
        float lo = sOut[(2 * k2) * 16 + cc];
        float hi = sOut[(2 * k2 + 1) * 16 + cc];
        g_Mvh[d * 2048 + k2 * 64 + g0 + cc] = h2u(__floats2half2_rn(lo, hi));
    }
}

// ---------------------------------------------------------------------------
// Kernel A: fused dual GEMM per 64-row tile, fp16 m16n8k16, 1 mma per (nt,mat).
//   xv = (x*mask)@Mv -> g_xvh (fp16);  skip = (x*mask)@Ws -> g_skip (fp32)
// sXh [64][36] half2 (pad 36 -> A-frag banks 4*gid+tig all distinct);
// sWm/sWs [32][72] half2 (pad 72 -> B-frag banks 8*tig+gid all distinct).
// 32 MMA/warp at full fp16 rate -> tensor ~4us; kernel DRAM-stream bound.
// ---------------------------------------------------------------------------
__global__ __launch_bounds__(256) void kernelA(
    const float* __restrict__ x0, const float* __restrict__ x1, const float* __restrict__ x2,
    const float* __restrict__ mask)
{
    __shared__ __align__(16) uint32_t sXh[64 * 36];
    __shared__ __align__(16) uint32_t sWm[32 * 72];
    __shared__ __align__(16) uint32_t sWs[32 * 72];

    int bx = blockIdx.x, tid = threadIdx.x;
    int tile, md, moff, dsel;
    const float* x;
    if (bx < 256)       { tile = bx;        x = x0; dsel = 0; md = 1; moff = 0; }
    else if (bx < 1024) { tile = bx - 256;  x = x1; dsel = 1; md = 3; moff = 1; }
    else                { tile = bx - 1024; x = x2; dsel = 2; md = 5; moff = 4; }
    int row0 = tile * 64;
    const uint32_t* Wm  = g_Mvh + dsel * 2048;
    const uint32_t* Wsh = g_Wsh + dsel * 2048;

    // X tile: load fp32, apply mask, store packed half2
    const float* xb = x + (size_t)row0 * 64;
    #pragma unroll
    for (int it = 0; it < 4; ++it) {
        int i = tid * 4 + it * 1024;
        int r = i >> 6, c = i & 63;
        float4 v = *(const float4*)(xb + i);
        float mk = mask[(row0 + r) / md];
        int kk = c >> 1;
        sXh[r * 36 + kk]     = h2u(__floats2half2_rn(v.x * mk, v.y * mk));
        sXh[r * 36 + kk + 1] = h2u(__floats2half2_rn(v.z * mk, v.w * mk));
    }
    // Weights: pre-packed half2, vectorized stage
    #pragma unroll
    for (int it = 0; it < 2; ++it) {
        int i = tid * 4 + it * 1024;
        int k2 = i >> 6, cc = i & 63;
        *(uint4*)(sWm + k2 * 72 + cc) = *(const uint4*)(Wm + i);
        *(uint4*)(sWs + k2 * 72 + cc) = *(const uint4*)(Wsh + i);
    }
    __syncthreads();

    int wp = tid >> 5, lane = tid & 31;
    int gid = lane >> 2, tig = lane & 3;
    int m0 = (wp & 3) * 16;         // 16-row m-tile
    int cq = (wp >> 2) * 32;        // 32-col n-half (4 n-tiles of 8)

    float accM[4][4], accS[4][4];
    #pragma unroll
    for (int nt = 0; nt < 4; ++nt)
        #pragma unroll
        for (int q = 0; q < 4; ++q) { accM[nt][q] = 0.f; accS[nt][q] = 0.f; }

    #pragma unroll
    for (int kh = 0; kh < 32; kh += 8) {       // half2-index base (k0 = 2*kh)
        uint32_t A0 = sXh[(m0 + gid) * 36 + kh + tig];
        uint32_t A1 = sXh[(m0 + gid + 8) * 36 + kh + tig];
        uint32_t A2 = sXh[(m0 + gid) * 36 + kh + tig + 4];
        uint32_t A3 = sXh[(m0 + gid + 8) * 36 + kh + tig + 4];

        #pragma unroll
        for (int nt = 0; nt < 4; ++nt) {
            int c0 = cq + nt * 8;
            uint32_t bm0 = sWm[(kh + tig) * 72 + c0 + gid];
            uint32_t bm1 = sWm[(kh + tig + 4) * 72 + c0 + gid];
            MMA_F16(accM[nt], A0, A1, A2, A3, bm0, bm1);
            uint32_t bs0 = sWs[(kh + tig) * 72 + c0 + gid];
            uint32_t bs1 = sWs[(kh + tig + 4) * 72 + c0 + gid];
            MMA_F16(accS[nt], A0, A1, A2, A3, bs0, bs1);
        }
    }

    // Epilogue: D frag rows (m0+gid), (m0+gid+8); cols cq+nt*8+2tig, +1
    int r0g = row0 + m0 + gid;
    int r1g = r0g + 8;
    int bn0 = r0g / md, bn1 = r1g / md;
    int base0 = (bn0 * 9 + moff + (r0g - bn0 * md)) * 64;
    int base1 = (bn1 * 9 + moff + (r1g - bn1 * md)) * 64;
    #pragma unroll
    for (int nt = 0; nt < 4; ++nt) {
        int col = cq + nt * 8 + 2 * tig;
        *(__half2*)(g_xvh + base0 + col) = __floats2half2_rn(accM[nt][0], accM[nt][1]);
        *(__half2*)(g_xvh + base1 + col) = __floats2half2_rn(accM[nt][2], accM[nt][3]);
        *(float2*)(g_skip + base0 + col) = make_float2(accS[nt][0], accS[nt][1]);
        *(float2*)(g_skip + base1 + col) = make_float2(accS[nt][2], accS[nt][3]);
    }
}

// ---------------------------------------------------------------------------
// Kernel B (R5 known-good, measured 57.4us): one block per point, 288 threads.
// ---------------------------------------------------------------------------
__global__ __launch_bounds__(288) void kernelB(
    const float* __restrict__ points, const int* __restrict__ pidx,
    const float* __restrict__ mask, float* __restrict__ out)
{
    __shared__ float sw[32];
    __shared__ int   srow[32];
    __shared__ int   snnz;
    __shared__ __align__(8) float vbuf[576];
    __shared__ __align__(8) float fbuf[192];

    int bn = blockIdx.x;
    int tid = threadIdx.x;

    if (tid < 32) {
        int idx  = pidx[bn * 32 + tid];
        int b    = bn >> 12;                 // N = 4096
        int prow = (b << 12) + idx;
        float cx = points[bn * 3 + 0], cy = points[bn * 3 + 1], cz = points[bn * 3 + 2];
        float dx = points[prow * 3 + 0] - cx;
        float dy = points[prow * 3 + 1] - cy;
        float dz = points[prow * 3 + 2] - cz;
        float r  = sqrtf(fmaf(dx, dx, fmaf(dy, dy, fmaf(dz, dz, 1e-12f))));
        float w  = 1.0f - r / 0.4f;
        bool act = w > 0.0f;
        unsigned bal = __ballot_sync(0xffffffffu, act);
        int pos = __popc(bal & ((1u << tid) - 1u));
        if (act) { sw[pos] = w; srow[pos] = prow * 576; }
        if (tid == 0) snnz = __popc(bal);
    }
    __syncthreads();

    int m = tid >> 5, j = tid & 31;
    int off = m * 64 + j * 2;
    int nnz = snnz;

    float ax = 0.f, ay = 0.f;
    int i = 0;
    for (; i + 4 <= nnz; i += 4) {
        float w0 = sw[i + 0], w1 = sw[i + 1], w2 = sw[i + 2], w3 = sw[i + 3];
        float2 p0 = __half22float2(*(const __half2*)(g_xvh + srow[i + 0] + off));
        float2 p1 = __half22float2(*(const __half2*)(g_xvh + srow[i + 1] + off));
        float2 p2 = __half22float2(*(const __half2*)(g_xvh + srow[i + 2] + off));
        float2 p3 = __half22float2(*(const __half2*)(g_xvh + srow[i + 3] + off));
        ax = fmaf(w0, p0.x, ax); ay = fmaf(w0, p0.y, ay);
        ax = fmaf(w1, p1.x, ax); ay = fmaf(w1, p1.y, ay);
        ax = fmaf(w2, p2.x, ax); ay = fmaf(w2, p2.y, ay);
        ax = fmaf(w3, p3.x, ax); ay = fmaf(w3, p3.y, ay);
    }
    for (; i < nnz; ++i) {
        float w0 = sw[i];
        float2 p0 = __half22float2(*(const __half2*)(g_xvh + srow[i] + off));
        ax = fmaf(w0, p0.x, ax); ay = fmaf(w0, p0.y, ay);
    }
    vbuf[off] = ax; vbuf[off + 1] = ay;
    __syncthreads();

    if (tid < 192) {
        int d  = tid >> 6, co = tid & 63;
        int m0 = (d == 0) ? 0 : (d == 1 ? 1 : 4);
        int mc = (d == 0) ? 1 : (d == 1 ? 3 : 5);
        float S = 0.f;
        for (int mm = 0; mm < mc; ++mm) {
            float v = vbuf[(m0 + mm) * 64 + co];
            S = fmaf(v, v, S);
        }
        float scale = rsqrtf(S + 0.01f);
        float f = scale;
        if (d > 0) {
            float S2 = S * scale * scale;             // = sum of normalized v^2
            float nn = sqrtf(S2 + 0.01f);
            f = scale * (1.0f / (1.0f + __expf(-nn)));
        }
        fbuf[tid] = f;
    }
    __syncthreads();

    float mk = mask[bn];
    int d = (m == 0) ? 0 : (m < 4 ? 1 : 2);
    float2 f2 = *(const float2*)&fbuf[d * 64 + 2 * j];
    float a0 = ax * f2.x, a1 = ay * f2.y;
    if (m == 0) { a0 = fmaxf(a0, 0.f); a1 = fmaxf(a1, 0.f); }

    float2 sk = *(const float2*)(g_skip + bn * 576 + off);
    float o0 = (a0 + sk.x) * mk;
    float o1 = (a1 + sk.y) * mk;

    float* op;
    if (m == 0)      op = out + bn * 64 + 2 * j;
    else if (m < 4)  op = out + OUT1_OFF + (bn * 3 + (m - 1)) * 64 + 2 * j;
    else             op = out + OUT2_OFF + (bn * 5 + (m - 4)) * 64 + 2 * j;
    *(float2*)op = make_float2(o0, o1);
}

// ---------------------------------------------------------------------------
extern "C" void kernel_launch(void* const* d_in, const int* in_sizes, int n_in,
                              void* d_out, int out_size) {
    const float* x0     = (const float*)d_in[0];
    const float* x1     = (const float*)d_in[1];
    const float* x2     = (const float*)d_in[2];
    const float* points = (const float*)d_in[3];
    const int*   pidx   = (const int*)  d_in[4];
    const float* mask   = (const float*)d_in[5];
    const float* Wc0    = (const float*)d_in[6];
    const float* Wc1    = (const float*)d_in[7];
    const float* Wc2    = (const float*)d_in[8];
    const float* Wv0    = (const float*)d_in[9];
    const float* Wv1    = (const float*)d_in[10];
    const float* Wv2    = (const float*)d_in[11];
    const float* Ws0    = (const float*)d_in[12];
    const float* Ws1    = (const float*)d_in[13];
    const float* Ws2    = (const float*)d_in[14];
    float* out = (float*)d_out;

    kernelM<<<12, 256>>>(Wc0, Wc1, Wc2, Wv0, Wv1, Wv2, Ws0, Ws1, Ws2);
    kernelA<<<2304, 256>>>(x0, x1, x2, mask);
    kernelB<<<16384, 288>>>(points, pidx, mask, out);
}

// round 14
// speedup vs baseline: 2.2954x; 1.3558x over previous
// R14: kernelB restructured to warp-per-point (register norm, zero barriers).
//      kernelA (fp16 MMA) and kernelM byte-identical to R13.
#include <cuda_runtime.h>
#include <cuda_fp16.h>
#include <cstdint>

#define BN_TOTAL 16384      // B*N = 4*4096
#define OUT1_OFF 1048576    // B*N*1*64
#define OUT2_OFF 4194304    // OUT1_OFF + B*N*3*64

// Packed half2 weights: [deg][k2=32][c=64], element = half2(W[2k2][c], W[2k2+1][c])
__device__ __align__(16) uint32_t g_Mvh[3 * 2048];
__device__ __align__(16) uint32_t g_Wsh[3 * 2048];
__device__ __align__(16) __half  g_xvh[BN_TOTAL * 9 * 64];   // fp16 gathered tensor
__device__ __align__(16) float   g_skip[BN_TOTAL * 9 * 64];  // fp32 skip path

__device__ __forceinline__ uint32_t h2u(__half2 h) { return *(uint32_t*)&h; }

#define MMA_F16(acc, a0, a1, a2, a3, b0, b1)                                    \
    asm volatile(                                                               \
        "mma.sync.aligned.m16n8k16.row.col.f32.f16.f16.f32 "                    \
        "{%0,%1,%2,%3}, {%4,%5,%6,%7}, {%8,%9}, {%0,%1,%2,%3};"                 \
        : "+f"((acc)[0]), "+f"((acc)[1]), "+f"((acc)[2]), "+f"((acc)[3])        \
        : "r"(a0), "r"(a1), "r"(a2), "r"(a3), "r"(b0), "r"(b1))

// ---------------------------------------------------------------------------
// Kernel M: Mv_d = Wconv_d @ Wv_d, then emit k-pair-packed half2 Mv and Ws.
// ---------------------------------------------------------------------------
__global__ __launch_bounds__(256) void kernelM(
    const float* __restrict__ Wc0, const float* __restrict__ Wc1,
    const float* __restrict__ Wc2, const float* __restrict__ Wv0,
    const float* __restrict__ Wv1, const float* __restrict__ Wv2,
    const float* __restrict__ Ws0, const float* __restrict__ Ws1,
    const float* __restrict__ Ws2)
{
    __shared__ float sWc[64 * 65];
    __shared__ __align__(16) float sWvS[64 * 16];
    __shared__ __align__(16) float sOut[64 * 16];
    int d = blockIdx.x >> 2, sl = blockIdx.x & 3;
    int g0 = sl * 16;
    const float* Wc = (d == 0) ? Wc0 : (d == 1 ? Wc1 : Wc2);
    const float* Wv = (d == 0) ? Wv0 : (d == 1 ? Wv1 : Wv2);
    const float* Ws = (d == 0) ? Ws0 : (d == 1 ? Ws1 : Ws2);
    int tid = threadIdx.x;

    #pragma unroll
    for (int it = 0; it < 16; ++it) {
        int i = tid + it * 256;
        int k = i & 63, c = i >> 6;
        sWc[c * 65 + k] = Wc[i];
    }
    {
        int i = tid * 4;
        int k = i >> 4, cc = i & 15;
        *(float4*)(sWvS + k * 16 + cc) = *(const float4*)(Wv + k * 64 + g0 + cc);
    }
    #pragma unroll
    for (int j = 0; j < 2; ++j) {
        int idx = tid + j * 256;
        int k2 = idx >> 4, cc = idx & 15;
        float lo = Ws[(2 * k2) * 64 + g0 + cc];
        float hi = Ws[(2 * k2 + 1) * 64 + g0 + cc];
        g_Wsh[d * 2048 + k2 * 64 + g0 + cc] = h2u(__floats2half2_rn(lo, hi));
    }
    __syncthreads();

    int c = tid & 63, cg = (tid >> 6) * 4;
    float4 acc = make_float4(0.f, 0.f, 0.f, 0.f);
    #pragma unroll 8
    for (int k = 0; k < 64; ++k) {
        float a = sWc[c * 65 + k];
        float4 b = *(const float4*)(sWvS + k * 16 + cg);
        acc.x = fmaf(a, b.x, acc.x);
        acc.y = fmaf(a, b.y, acc.y);
        acc.z = fmaf(a, b.z, acc.z);
        acc.w = fmaf(a, b.w, acc.w);
    }
    *(float4*)(sOut + c * 16 + cg) = acc;
    __syncthreads();

    #pragma unroll
    for (int j = 0; j < 2; ++j) {
        int idx = tid + j * 256;
        int k2 = idx >> 4, cc = idx & 15;
        float lo = sOut[(2 * k2) * 16 + cc];
        float hi = sOut[(2 * k2 + 1) * 16 + cc];
        g_Mvh[d * 2048 + k2 * 64 + g0 + cc] = h2u(__floats2half2_rn(lo, hi));
    }
}

// ---------------------------------------------------------------------------
// Kernel A: fused dual GEMM per 64-row tile, fp16 m16n8k16 (R13, 22.8us).
// ---------------------------------------------------------------------------
__global__ __launch_bounds__(256) void kernelA(
    const float* __restrict__ x0, const float* __restrict__ x1, const float* __restrict__ x2,
    const float* __restrict__ mask)
{
    __shared__ __align__(16) uint32_t sXh[64 * 36];
    __shared__ __align__(16) uint32_t sWm[32 * 72];
    __shared__ __align__(16) uint32_t sWs[32 * 72];

    int bx = blockIdx.x, tid = threadIdx.x;
    int tile, md, moff, dsel;
    const float* x;
    if (bx < 256)       { tile = bx;        x = x0; dsel = 0; md = 1; moff = 0; }
    else if (bx < 1024) { tile = bx - 256;  x = x1; dsel = 1; md = 3; moff = 1; }
    else                { tile = bx - 1024; x = x2; dsel = 2; md = 5; moff = 4; }
    int row0 = tile * 64;
    const uint32_t* Wm  = g_Mvh + dsel * 2048;
    const uint32_t* Wsh = g_Wsh + dsel * 2048;

    const float* xb = x + (size_t)row0 * 64;
    #pragma unroll
    for (int it = 0; it < 4; ++it) {
        int i = tid * 4 + it * 1024;
        int r = i >> 6, c = i & 63;
        float4 v = *(const float4*)(xb + i);
        float mk = mask[(row0 + r) / md];
        int kk = c >> 1;
        sXh[r * 36 + kk]     = h2u(__floats2half2_rn(v.x * mk, v.y * mk));
        sXh[r * 36 + kk + 1] = h2u(__floats2half2_rn(v.z * mk, v.w * mk));
    }
    #pragma unroll
    for (int it = 0; it < 2; ++it) {
        int i = tid * 4 + it * 1024;
        int k2 = i >> 6, cc = i & 63;
        *(uint4*)(sWm + k2 * 72 + cc) = *(const uint4*)(Wm + i);
        *(uint4*)(sWs + k2 * 72 + cc) = *(const uint4*)(Wsh + i);
    }
    __syncthreads();

    int wp = tid >> 5, lane = tid & 31;
    int gid = lane >> 2, tig = lane & 3;
    int m0 = (wp & 3) * 16;
    int cq = (wp >> 2) * 32;

    float accM[4][4], accS[4][4];
    #pragma unroll
    for (int nt = 0; nt < 4; ++nt)
        #pragma unroll
        for (int q = 0; q < 4; ++q) { accM[nt][q] = 0.f; accS[nt][q] = 0.f; }

    #pragma unroll
    for (int kh = 0; kh < 32; kh += 8) {
        uint32_t A0 = sXh[(m0 + gid) * 36 + kh + tig];
        uint32_t A1 = sXh[(m0 + gid + 8) * 36 + kh + tig];
        uint32_t A2 = sXh[(m0 + gid) * 36 + kh + tig + 4];
        uint32_t A3 = sXh[(m0 + gid + 8) * 36 + kh + tig + 4];

        #pragma unroll
        for (int nt = 0; nt < 4; ++nt) {
            int c0 = cq + nt * 8;
            uint32_t bm0 = sWm[(kh + tig) * 72 + c0 + gid];
            uint32_t bm1 = sWm[(kh + tig + 4) * 72 + c0 + gid];
            MMA_F16(accM[nt], A0, A1, A2, A3, bm0, bm1);
            uint32_t bs0 = sWs[(kh + tig) * 72 + c0 + gid];
            uint32_t bs1 = sWs[(kh + tig + 4) * 72 + c0 + gid];
            MMA_F16(accS[nt], A0, A1, A2, A3, bs0, bs1);
        }
    }

    int r0g = row0 + m0 + gid;
    int r1g = r0g + 8;
    int bn0 = r0g / md, bn1 = r1g / md;
    int base0 = (bn0 * 9 + moff + (r0g - bn0 * md)) * 64;
    int base1 = (bn1 * 9 + moff + (r1g - bn1 * md)) * 64;
    #pragma unroll
    for (int nt = 0; nt < 4; ++nt) {
        int col = cq + nt * 8 + 2 * tig;
        *(__half2*)(g_xvh + base0 + col) = __floats2half2_rn(accM[nt][0], accM[nt][1]);
        *(__half2*)(g_xvh + base1 + col) = __floats2half2_rn(accM[nt][2], accM[nt][3]);
        *(float2*)(g_skip + base0 + col) = make_float2(accS[nt][0], accS[nt][1]);
        *(float2*)(g_skip + base1 + col) = make_float2(accS[nt][2], accS[nt][3]);
    }
}

// ---------------------------------------------------------------------------
// Kernel B: WARP-PER-POINT. 2048 blocks x 256 thr (8 warps = 8 points).
//   lane j accumulates co pair (2j,2j+1) for ALL 9 m-rows (float2 acc[9]).
//   ballot + __fns register compaction; per-neighbor shfl broadcast;
//   normalization fully lane-local (no smem, no barriers).
// ---------------------------------------------------------------------------
__global__ __launch_bounds__(256) void kernelB(
    const float* __restrict__ points, const int* __restrict__ pidx,
    const float* __restrict__ mask, float* __restrict__ out)
{
    int bn   = blockIdx.x * 8 + (threadIdx.x >> 5);
    int lane = threadIdx.x & 31;

    // --- neighbor weights (warp-synchronous, register-compacted) ---
    int idx  = pidx[bn * 32 + lane];
    int prow = ((bn >> 12) << 12) + idx;
    float cx = points[bn * 3 + 0], cy = points[bn * 3 + 1], cz = points[bn * 3 + 2];
    float dx = points[prow * 3 + 0] - cx;
    float dy = points[prow * 3 + 1] - cy;
    float dz = points[prow * 3 + 2] - cz;
    float r  = sqrtf(fmaf(dx, dx, fmaf(dy, dy, fmaf(dz, dz, 1e-12f))));
    float w  = 1.0f - r * 2.5f;
    unsigned bal = __ballot_sync(0xffffffffu, w > 0.0f);
    int nnz = __popc(bal);
    int src = __fns(bal, 0, lane + 1) & 31;      // lane-th set bit
    float wc = __shfl_sync(0xffffffffu, w, src);
    int   rc = __shfl_sync(0xffffffffu, prow, src) * 288;   // half2 row offset

    // --- gather: 9 m-rows per lane, co pair = 2*lane ---
    const __half2* xbase = (const __half2*)g_xvh + lane;
    float2 acc[9];
    #pragma unroll
    for (int m = 0; m < 9; ++m) acc[m] = make_float2(0.f, 0.f);

    for (int i = 0; i < nnz; ++i) {
        float wi = __shfl_sync(0xffffffffu, wc, i);
        int   ri = __shfl_sync(0xffffffffu, rc, i);
        const __half2* p = xbase + ri;
        #pragma unroll
        for (int m = 0; m < 9; ++m) {
            float2 v = __half22float2(p[m * 32]);
            acc[m].x = fmaf(wi, v.x, acc[m].x);
            acc[m].y = fmaf(wi, v.y, acc[m].y);
        }
    }

    // --- lane-local normalization factors (per component) ---
    float f0x, f0y, f1x, f1y, f2x, f2y;
    {
        f0x = rsqrtf(acc[0].x * acc[0].x + 0.01f);
        f0y = rsqrtf(acc[0].y * acc[0].y + 0.01f);

        float Sx = acc[1].x * acc[1].x + acc[2].x * acc[2].x + acc[3].x * acc[3].x;
        float Sy = acc[1].y * acc[1].y + acc[2].y * acc[2].y + acc[3].y * acc[3].y;
        float scx = rsqrtf(Sx + 0.01f), scy = rsqrtf(Sy + 0.01f);
        float nnx = sqrtf(Sx * scx * scx + 0.01f), nny = sqrtf(Sy * scy * scy + 0.01f);
        f1x = scx / (1.0f + __expf(-nnx));
        f1y = scy / (1.0f + __expf(-nny));

        Sx = acc[4].x * acc[4].x + acc[5].x * acc[5].x + acc[6].x * acc[6].x
           + acc[7].x * acc[7].x + acc[8].x * acc[8].x;
        Sy = acc[4].y * acc[4].y + acc[5].y * acc[5].y + acc[6].y * acc[6].y
           + acc[7].y * acc[7].y + acc[8].y * acc[8].y;
        scx = rsqrtf(Sx + 0.01f); scy = rsqrtf(Sy + 0.01f);
        nnx = sqrtf(Sx * scx * scx + 0.01f); nny = sqrtf(Sy * scy * scy + 0.01f);
        f2x = scx / (1.0f + __expf(-nnx));
        f2y = scy / (1.0f + __expf(-nny));
    }

    // --- epilogue: a + skip, * mask ---
    float mk = mask[bn];
    const float* skp = g_skip + bn * 576 + 2 * lane;

    {   // deg0 (m=0): relu
        float2 sk = *(const float2*)(skp);
        float a0 = fmaxf(acc[0].x * f0x, 0.f);
        float a1 = fmaxf(acc[0].y * f0y, 0.f);
        *(float2*)(out + bn * 64 + 2 * lane) =
            make_float2((a0 + sk.x) * mk, (a1 + sk.y) * mk);
    }
    #pragma unroll
    for (int m = 1; m < 4; ++m) {   // deg1
        float2 sk = *(const float2*)(skp + m * 64);
        float a0 = acc[m].x * f1x, a1 = acc[m].y * f1y;
        *(float2*)(out + OUT1_OFF + (bn * 3 + (m - 1)) * 64 + 2 * lane) =
            make_float2((a0 + sk.x) * mk, (a1 + sk.y) * mk);
    }
    #pragma unroll
    for (int m = 4; m < 9; ++m) {   // deg2
        float2 sk = *(const float2*)(skp + m * 64);
        float a0 = acc[m].x * f2x, a1 = acc[m].y * f2y;
        *(float2*)(out + OUT2_OFF + (bn * 5 + (m - 4)) * 64 + 2 * lane) =
            make_float2((a0 + sk.x) * mk, (a1 + sk.y) * mk);
    }
}

// ---------------------------------------------------------------------------
extern "C" void kernel_launch(void* const* d_in, const int* in_sizes, int n_in,
                              void* d_out, int out_size) {
    const float* x0     = (const float*)d_in[0];
    const float* x1     = (const float*)d_in[1];
    const float* x2     = (const float*)d_in[2];
    const float* points = (const float*)d_in[3];
    const int*   pidx   = (const int*)  d_in[4];
    const float* mask   = (const float*)d_in[5];
    const float* Wc0    = (const float*)d_in[6];
    const float* Wc1    = (const float*)d_in[7];
    const float* Wc2    = (const float*)d_in[8];
    const float* Wv0    = (const float*)d_in[9];
    const float* Wv1    = (const float*)d_in[10];
    const float* Wv2    = (const float*)d_in[11];
    const float* Ws0    = (const float*)d_in[12];
    const float* Ws1    = (const float*)d_in[13];
    const float* Ws2    = (const float*)d_in[14];
    float* out = (float*)d_out;

    kernelM<<<12, 256>>>(Wc0, Wc1, Wc2, Wv0, Wv1, Wv2, Ws0, Ws1, Ws2);
    kernelA<<<2304, 256>>>(x0, x1, x2, mask);
    kernelB<<<2048, 256>>>(points, pidx, mask, out);
}